// round 10
// baseline (speedup 1.0000x reference)
#include <cuda_runtime.h>
#include <cstdint>

#define N_NODES 32768
#define B_GRAPHS 16
#define NP_G 2048
#define IN_DIM 32
#define HID 128
#define OUT_DIM 64
#define KNN 16
#define NPAIRS 100000
#define NEG_SLOPE 0.2f

// ---------------- static scratch (allocation-free) ----------------
__device__ float g_Wf  [IN_DIM * HID];        // fused W0@gatW
__device__ float g_bf  [HID];                 // fused b0@gatW
__device__ float g_xl  [N_NODES * HID];
__device__ float g_asrc[N_NODES];
__device__ float g_adst[N_NODES];
__device__ float g_gat [N_NODES * HID];
__device__ float g_e1  [N_NODES * 4 * HID];
__device__ float g_e2  [N_NODES * 2 * HID];
__device__ float g_emb [N_NODES * OUT_DIM];

// ---------------- fuse Wf = W0@gatW, bf = b0@gatW ----------------
// h (first linear) is only consumed by the gat lin (kNN is degenerate, see gat_k),
// so fold the two linears: xl = x @ (W0@gatW) + (b0@gatW).
__global__ __launch_bounds__(128) void fuseW_k(
    const float* __restrict__ W0, const float* __restrict__ b0,
    const float* __restrict__ gatW, float* __restrict__ Wf, float* __restrict__ bf)
{
    const int i = blockIdx.x;
    const int j = threadIdx.x;
    const float* rowp = (i < IN_DIM) ? (W0 + i * HID) : b0;
    float s = 0.0f;
    #pragma unroll 8
    for (int k = 0; k < HID; k++)
        s += rowp[k] * gatW[k * HID + j];
    if (i < IN_DIM) Wf[i * HID + j] = s;
    else            bf[j] = s;
}

// ---------------- tiled SGEMM: C = act(A@B + bias) ----------------
// BM=128, BN=64, BK=16. 256 threads, 8x4 per thread.
// All dims are multiples of the tiles -> no bounds checks.
// MODE 0: +bias (bias may be null), MODE 1: relu(+bias)
template <int MODE>
__global__ __launch_bounds__(256) void gemm_k(
    const float* __restrict__ A, const float* __restrict__ B,
    const float* __restrict__ bias, float* __restrict__ C,
    int M, int Kd, int Nd)
{
    __shared__ float As[16][132];   // A^T tile As[k][r], padded rows
    __shared__ float Bs[16][68];    // Bs[k][c], padded rows

    const int tid = threadIdx.x;
    const int tx = tid & 15, ty = tid >> 4;
    const int row0 = blockIdx.y * 128, col0 = blockIdx.x * 64;

    float acc[8][4] = {};

    for (int k0 = 0; k0 < Kd; k0 += 16) {
        #pragma unroll
        for (int i = 0; i < 8; i++) {
            int t = tid + i * 256;
            int r = t >> 4, c = t & 15;
            As[c][r] = A[(row0 + r) * Kd + k0 + c];
        }
        #pragma unroll
        for (int i = 0; i < 4; i++) {
            int t = tid + i * 256;
            int r = t >> 6, c = t & 63;
            Bs[r][c] = B[(k0 + r) * Nd + col0 + c];
        }
        __syncthreads();

        #pragma unroll
        for (int k = 0; k < 16; k++) {
            float4 a0 = *(const float4*)&As[k][ty * 8];
            float4 a1 = *(const float4*)&As[k][ty * 8 + 4];
            float4 b4 = *(const float4*)&Bs[k][tx * 4];
            float av[8] = {a0.x, a0.y, a0.z, a0.w, a1.x, a1.y, a1.z, a1.w};
            float bv[4] = {b4.x, b4.y, b4.z, b4.w};
            #pragma unroll
            for (int i = 0; i < 8; i++)
                #pragma unroll
                for (int j = 0; j < 4; j++)
                    acc[i][j] += av[i] * bv[j];
        }
        __syncthreads();
    }

    float4 bb = make_float4(0.f, 0.f, 0.f, 0.f);
    if (bias) bb = *(const float4*)&bias[col0 + tx * 4];

    #pragma unroll
    for (int i = 0; i < 8; i++) {
        int r = row0 + ty * 8 + i;
        float4 v;
        v.x = acc[i][0] + bb.x;
        v.y = acc[i][1] + bb.y;
        v.z = acc[i][2] + bb.z;
        v.w = acc[i][3] + bb.w;
        if (MODE == 1) {
            v.x = fmaxf(v.x, 0.f); v.y = fmaxf(v.y, 0.f);
            v.z = fmaxf(v.z, 0.f); v.w = fmaxf(v.w, 0.f);
        }
        *(float4*)&C[r * Nd + col0 + tx * 4] = v;
    }
}

// ---------------- per-node attention dot products ----------------
__global__ __launch_bounds__(256) void attdot_k(
    const float* __restrict__ xl, const float* __restrict__ att_src,
    const float* __restrict__ att_dst, float* __restrict__ asrc,
    float* __restrict__ adst)
{
    int n = blockIdx.x * 8 + (threadIdx.x >> 5);
    int lane = threadIdx.x & 31;
    float s = 0.f, d = 0.f;
    #pragma unroll
    for (int q = 0; q < 4; q++) {
        int dd = lane + q * 32;
        float v = xl[n * HID + dd];
        s += v * att_src[dd];
        d += v * att_dst[dd];
    }
    #pragma unroll
    for (int o = 16; o > 0; o >>= 1) {
        s += __shfl_down_sync(0xffffffffu, s, o);
        d += __shfl_down_sync(0xffffffffu, d, o);
    }
    if (lane == 0) { asrc[n] = s; adst[n] = d; }
}

// ---------------- GAT with degenerate (NaN-topk) neighbor set ----------------
// The reference's d2 + eye*inf produces +qNaN off-diagonal (0*inf) and +inf
// diag; -d2 has qNaN off-diag, -inf diag. XLA GPU top_k total-order sort
// (qNaN > inf, ties -> ascending index) keeps the 16 lowest-index
// non-diagonal entries:
//   local n >= 16: neighbors {0..15}; + self loop -> {0..15} U {n}
//   local n <  16: neighbors {0..16}\{n}; + self loop -> {0..16} each once
// (Round-7 run with {0..15}+dup-self for n<16 gave rel_err 2.6e-2 matching
//  exactly the predicted 256/32768 affected nodes; this is the corrected set.)
__global__ __launch_bounds__(256) void gat_k(
    const float* __restrict__ xl, const float* __restrict__ asrc,
    const float* __restrict__ adst, const float* __restrict__ gat_b,
    float* __restrict__ out)
{
    __shared__ float sx[KNN + 1][HID];   // local nodes 0..16, shared by whole graph
    __shared__ float ss[KNN + 1];

    const int nodebase = blockIdx.x * 8;              // 8 nodes per block (same graph)
    const int g = nodebase / NP_G;
    const int base = g * NP_G;
    const int tid = threadIdx.x;

    for (int t = tid; t < (KNN + 1) * HID; t += 256)
        sx[t >> 7][t & 127] = xl[(base + (t >> 7)) * HID + (t & 127)];
    if (tid < KNN + 1) ss[tid] = asrc[base + tid];
    __syncthreads();

    const int warp = tid >> 5, lane = tid & 31;
    const int n = nodebase + warp;
    const int ln = n - base;                          // local id
    const bool low = (ln < 16);                       // low rows attend {0..16}
    const float adn = adst[n];

    float l = -1e30f;
    if (lane < 17) {
        float e = (low || lane < 16) ? ss[lane] : asrc[n];
        float z = e + adn;
        l = z >= 0.0f ? z : NEG_SLOPE * z;
    }
    float m = l;
    #pragma unroll
    for (int o = 16; o > 0; o >>= 1) m = fmaxf(m, __shfl_xor_sync(0xffffffffu, m, o));
    float w = (lane < 17) ? __expf(l - m) : 0.0f;
    float s = w;
    #pragma unroll
    for (int o = 16; o > 0; o >>= 1) s += __shfl_xor_sync(0xffffffffu, s, o);
    w /= s;

    float xn[4], acc[4] = {0.f, 0.f, 0.f, 0.f};
    #pragma unroll
    for (int q = 0; q < 4; q++) xn[q] = xl[n * HID + lane + q * 32];

    #pragma unroll
    for (int k = 0; k < 17; k++) {
        float wk = __shfl_sync(0xffffffffu, w, k);
        #pragma unroll
        for (int q = 0; q < 4; q++) {
            float v = (low || k < 16) ? sx[k][lane + q * 32] : xn[q];
            acc[q] += wk * v;
        }
    }
    #pragma unroll
    for (int q = 0; q < 4; q++) {
        int dd = lane + q * 32;
        out[n * HID + dd] = acc[q] + gat_b[dd];
    }
}

// ---------------- pair gather + labels, dtype-adaptive ----------------
// pairs_indices may be int32 (JAX x64 off) or int64; self-detect: int64 LE
// storage (values < 2^31) has zero high-words in all odd int32 slots.
// out layout: [2, P, OUT] pair embeddings, then [P] labels.
__global__ __launch_bounds__(256) void pairs_k(
    const float* __restrict__ emb, const int* __restrict__ pidx,
    const float* __restrict__ labels, float* __restrict__ outp)
{
    int orv = 0;
    #pragma unroll
    for (int q = 0; q < 8; q++) orv |= pidx[2 * q + 1];
    const bool is64 = (orv == 0);

    long long rowid = (long long)blockIdx.x * 16 + (threadIdx.x >> 4);
    int lane = threadIdx.x & 15;
    const long long nrows = 2LL * NPAIRS;
    if (rowid < nrows) {
        int s = (int)(rowid / NPAIRS);
        int p = (int)(rowid - (long long)s * NPAIRS);
        int e = p * 2 + s;                       // logical element index in [P,2]
        int node = is64 ? pidx[2 * e] : pidx[e]; // int64: low word at slot 2e
        float4 v = *(const float4*)&emb[(long long)node * OUT_DIM + lane * 4];
        *(float4*)&outp[rowid * OUT_DIM + lane * 4] = v;
    } else {
        long long li = (rowid - nrows) * 16 + lane;
        if (li < NPAIRS)
            outp[2LL * NPAIRS * OUT_DIM + li] = labels[li];
    }
}

// ---------------- launch ----------------
extern "C" void kernel_launch(void* const* d_in, const int* in_sizes, int n_in,
                              void* d_out, int out_size)
{
    const float* x       = (const float*)d_in[0];
    // d_in[1] = batch (layout fixed, unused)
    const int*   pairs   = (const int*)d_in[2];     // int32 view; width self-detected
    const float* labels  = (const float*)d_in[3];
    const float* W0      = (const float*)d_in[4];
    const float* b0      = (const float*)d_in[5];
    const float* gatW    = (const float*)d_in[6];
    const float* att_src = (const float*)d_in[7];
    const float* att_dst = (const float*)d_in[8];
    const float* gatb    = (const float*)d_in[9];
    const float* W1      = (const float*)d_in[10];
    const float* b1      = (const float*)d_in[11];
    const float* W2      = (const float*)d_in[12];
    const float* b2      = (const float*)d_in[13];
    const float* W3      = (const float*)d_in[14];
    const float* b3      = (const float*)d_in[15];
    float* out = (float*)d_out;

    float *Wf, *bf, *xl, *asrc, *adst, *gat, *e1, *e2, *emb;
    cudaGetSymbolAddress((void**)&Wf,   g_Wf);
    cudaGetSymbolAddress((void**)&bf,   g_bf);
    cudaGetSymbolAddress((void**)&xl,   g_xl);
    cudaGetSymbolAddress((void**)&asrc, g_asrc);
    cudaGetSymbolAddress((void**)&adst, g_adst);
    cudaGetSymbolAddress((void**)&gat,  g_gat);
    cudaGetSymbolAddress((void**)&e1,   g_e1);
    cudaGetSymbolAddress((void**)&e2,   g_e2);
    cudaGetSymbolAddress((void**)&emb,  g_emb);

    const int M = N_NODES;

    // 0. fused weight: Wf = W0@gatW [32,128], bf = b0@gatW [128]
    fuseW_k<<<IN_DIM + 1, HID>>>(W0, b0, gatW, Wf, bf);
    // 1. xl = x @ Wf + bf            [32768,32]@[32,128]
    gemm_k<0><<<dim3(HID / 64, M / 128), 256>>>(x, Wf, bf, xl, M, IN_DIM, HID);
    // 2. a_src / a_dst
    attdot_k<<<M / 8, 256>>>(xl, att_src, att_dst, asrc, adst);
    // 3. attention aggregate
    gat_k<<<M / 8, 256>>>(xl, asrc, adst, gatb, gat);
    // 4. MLP
    gemm_k<1><<<dim3(4 * HID / 64, M / 128), 256>>>(gat, W1, b1, e1, M, HID, 4 * HID);
    gemm_k<1><<<dim3(2 * HID / 64, M / 128), 256>>>(e1, W2, b2, e2, M, 4 * HID, 2 * HID);
    gemm_k<0><<<dim3(OUT_DIM / 64, M / 128), 256>>>(e2, W3, b3, emb, M, 2 * HID, OUT_DIM);
    // 5. gather pairs + labels
    long long nrows = 2LL * NPAIRS + (NPAIRS + 15) / 16;
    int nblk = (int)((nrows + 15) / 16);
    pairs_k<<<nblk, 256>>>(emb, pairs, labels, out);
}

// round 15
// speedup vs baseline: 1.1347x; 1.1347x over previous
#include <cuda_runtime.h>
#include <cstdint>

#define N_NODES 32768
#define B_GRAPHS 16
#define NP_G 2048
#define IN_DIM 32
#define HID 128
#define OUT_DIM 64
#define KNN 16
#define NPAIRS 100000
#define NEG_SLOPE 0.2f

// ---------------- static scratch (allocation-free) ----------------
__device__ float g_Wf  [IN_DIM * HID];
__device__ float g_bf  [HID];
__device__ float g_xl  [N_NODES * HID];
__device__ float g_asrc[N_NODES];
__device__ float g_adst[N_NODES];
__device__ float g_gat [N_NODES * HID];
__device__ float g_e1  [N_NODES * 4 * HID];
__device__ float g_e2  [N_NODES * 2 * HID];
__device__ float g_emb [N_NODES * OUT_DIM];

// ---------------- fuse Wf = W0@gatW, bf = b0@gatW ----------------
__global__ __launch_bounds__(128) void fuseW_k(
    const float* __restrict__ W0, const float* __restrict__ b0,
    const float* __restrict__ gatW, float* __restrict__ Wf, float* __restrict__ bf)
{
    const int i = blockIdx.x;
    const int j = threadIdx.x;
    const float* rowp = (i < IN_DIM) ? (W0 + i * HID) : b0;
    float s = 0.0f;
    #pragma unroll 8
    for (int k = 0; k < HID; k++)
        s += rowp[k] * gatW[k * HID + j];
    if (i < IN_DIM) Wf[i * HID + j] = s;
    else            bf[j] = s;
}

// ---------------- fp32 tiled SGEMM (kept for xl: K=32, mem-bound) -----------
template <int MODE>
__global__ __launch_bounds__(256) void gemm_k(
    const float* __restrict__ A, const float* __restrict__ B,
    const float* __restrict__ bias, float* __restrict__ C,
    int M, int Kd, int Nd)
{
    __shared__ float As[16][132];
    __shared__ float Bs[16][68];

    const int tid = threadIdx.x;
    const int tx = tid & 15, ty = tid >> 4;
    const int row0 = blockIdx.y * 128, col0 = blockIdx.x * 64;

    float acc[8][4] = {};

    for (int k0 = 0; k0 < Kd; k0 += 16) {
        #pragma unroll
        for (int i = 0; i < 8; i++) {
            int t = tid + i * 256;
            int r = t >> 4, c = t & 15;
            As[c][r] = A[(row0 + r) * Kd + k0 + c];
        }
        #pragma unroll
        for (int i = 0; i < 4; i++) {
            int t = tid + i * 256;
            int r = t >> 6, c = t & 63;
            Bs[r][c] = B[(k0 + r) * Nd + col0 + c];
        }
        __syncthreads();

        #pragma unroll
        for (int k = 0; k < 16; k++) {
            float4 a0 = *(const float4*)&As[k][ty * 8];
            float4 a1 = *(const float4*)&As[k][ty * 8 + 4];
            float4 b4 = *(const float4*)&Bs[k][tx * 4];
            float av[8] = {a0.x, a0.y, a0.z, a0.w, a1.x, a1.y, a1.z, a1.w};
            float bv[4] = {b4.x, b4.y, b4.z, b4.w};
            #pragma unroll
            for (int i = 0; i < 8; i++)
                #pragma unroll
                for (int j = 0; j < 4; j++)
                    acc[i][j] += av[i] * bv[j];
        }
        __syncthreads();
    }

    float4 bb = make_float4(0.f, 0.f, 0.f, 0.f);
    if (bias) bb = *(const float4*)&bias[col0 + tx * 4];

    #pragma unroll
    for (int i = 0; i < 8; i++) {
        int r = row0 + ty * 8 + i;
        float4 v;
        v.x = acc[i][0] + bb.x;
        v.y = acc[i][1] + bb.y;
        v.z = acc[i][2] + bb.z;
        v.w = acc[i][3] + bb.w;
        if (MODE == 1) {
            v.x = fmaxf(v.x, 0.f); v.y = fmaxf(v.y, 0.f);
            v.z = fmaxf(v.z, 0.f); v.w = fmaxf(v.w, 0.f);
        }
        *(float4*)&C[r * Nd + col0 + tx * 4] = v;
    }
}

// ------------- split-tf32 tensor-core GEMM: C = act(A@B + bias) -------------
// BM=128, BN=64, BK=32; 8 warps in 4(m)x2(n), each warp 32x32 via
// mma.sync.m16n8k8 tf32. Markidis 3-term split (hi*hi + hi*lo + lo*hi) for
// ~fp32 accuracy (error ~eps_tf32^2). fp32 smem tiles; split at fragment load.
__device__ __forceinline__ void split_tf32(float x, uint32_t& hi, uint32_t& lo) {
    uint32_t h;
    asm("cvt.rna.tf32.f32 %0, %1;" : "=r"(h) : "f"(x));
    float hf = __uint_as_float(h);            // tf32 value is fp32-representable
    uint32_t l;
    asm("cvt.rna.tf32.f32 %0, %1;" : "=r"(l) : "f"(x - hf));
    hi = h; lo = l;
}

#define MMA_TF32(C0, C1, C2, C3, A0, A1, A2, A3, B0, B1)                      \
    asm volatile(                                                             \
        "mma.sync.aligned.m16n8k8.row.col.f32.tf32.tf32.f32 "                 \
        "{%0,%1,%2,%3}, {%4,%5,%6,%7}, {%8,%9}, {%0,%1,%2,%3};"               \
        : "+f"(C0), "+f"(C1), "+f"(C2), "+f"(C3)                              \
        : "r"(A0), "r"(A1), "r"(A2), "r"(A3), "r"(B0), "r"(B1))

template <int MODE>
__global__ __launch_bounds__(256) void gemm_tc_k(
    const float* __restrict__ A, const float* __restrict__ B,
    const float* __restrict__ bias, float* __restrict__ C,
    int M, int Kd, int Nd)
{
    __shared__ float As[128][36];   // A[row][k] fp32, pad 36
    __shared__ float Bs[32][68];    // B[k][n]  fp32, pad 68

    const int tid  = threadIdx.x;
    const int lane = tid & 31, warp = tid >> 5;
    const int wm = warp & 3, wn = warp >> 2;       // 4 x 2 warp grid
    const int g  = lane >> 2, t4 = lane & 3;
    const int row0 = blockIdx.y * 128, col0 = blockIdx.x * 64;

    float c[2][4][4] = {};

    for (int k0 = 0; k0 < Kd; k0 += 32) {
        #pragma unroll
        for (int i = 0; i < 4; i++) {
            int idx = tid + i * 256;
            int r = idx >> 3, c4 = (idx & 7) * 4;
            float4 v = *(const float4*)&A[(row0 + r) * Kd + k0 + c4];
            As[r][c4 + 0] = v.x; As[r][c4 + 1] = v.y;
            As[r][c4 + 2] = v.z; As[r][c4 + 3] = v.w;
        }
        #pragma unroll
        for (int i = 0; i < 2; i++) {
            int idx = tid + i * 256;
            int r = idx >> 4, c4 = (idx & 15) * 4;
            float4 v = *(const float4*)&B[(k0 + r) * Nd + col0 + c4];
            Bs[r][c4 + 0] = v.x; Bs[r][c4 + 1] = v.y;
            Bs[r][c4 + 2] = v.z; Bs[r][c4 + 3] = v.w;
        }
        __syncthreads();

        #pragma unroll
        for (int kk = 0; kk < 32; kk += 8) {
            uint32_t ah[2][4], al[2][4], bh[4][2], bl[4][2];
            #pragma unroll
            for (int mi = 0; mi < 2; mi++) {
                int rb = wm * 32 + mi * 16;
                split_tf32(As[rb + g    ][kk + t4    ], ah[mi][0], al[mi][0]);
                split_tf32(As[rb + g + 8][kk + t4    ], ah[mi][1], al[mi][1]);
                split_tf32(As[rb + g    ][kk + t4 + 4], ah[mi][2], al[mi][2]);
                split_tf32(As[rb + g + 8][kk + t4 + 4], ah[mi][3], al[mi][3]);
            }
            #pragma unroll
            for (int ni = 0; ni < 4; ni++) {
                int cb = wn * 32 + ni * 8 + g;
                split_tf32(Bs[kk + t4    ][cb], bh[ni][0], bl[ni][0]);
                split_tf32(Bs[kk + t4 + 4][cb], bh[ni][1], bl[ni][1]);
            }
            #pragma unroll
            for (int mi = 0; mi < 2; mi++)
                #pragma unroll
                for (int ni = 0; ni < 4; ni++) {
                    float* cc = c[mi][ni];
                    // hi*hi + hi*lo + lo*hi (lo*lo ~ eps^2, negligible)
                    MMA_TF32(cc[0], cc[1], cc[2], cc[3],
                             ah[mi][0], ah[mi][1], ah[mi][2], ah[mi][3],
                             bh[ni][0], bh[ni][1]);
                    MMA_TF32(cc[0], cc[1], cc[2], cc[3],
                             ah[mi][0], ah[mi][1], ah[mi][2], ah[mi][3],
                             bl[ni][0], bl[ni][1]);
                    MMA_TF32(cc[0], cc[1], cc[2], cc[3],
                             al[mi][0], al[mi][1], al[mi][2], al[mi][3],
                             bh[ni][0], bh[ni][1]);
                }
        }
        __syncthreads();
    }

    #pragma unroll
    for (int mi = 0; mi < 2; mi++) {
        #pragma unroll
        for (int ni = 0; ni < 4; ni++) {
            int r  = row0 + wm * 32 + mi * 16 + g;
            int cc = col0 + wn * 32 + ni * 8 + 2 * t4;
            float b0 = bias ? bias[cc]     : 0.f;
            float b1 = bias ? bias[cc + 1] : 0.f;
            float v0 = c[mi][ni][0] + b0, v1 = c[mi][ni][1] + b1;
            float v2 = c[mi][ni][2] + b0, v3 = c[mi][ni][3] + b1;
            if (MODE == 1) {
                v0 = fmaxf(v0, 0.f); v1 = fmaxf(v1, 0.f);
                v2 = fmaxf(v2, 0.f); v3 = fmaxf(v3, 0.f);
            }
            *(float2*)&C[(long long)r * Nd + cc]       = make_float2(v0, v1);
            *(float2*)&C[(long long)(r + 8) * Nd + cc] = make_float2(v2, v3);
        }
    }
}

// ---------------- per-node attention dot products ----------------
__global__ __launch_bounds__(256) void attdot_k(
    const float* __restrict__ xl, const float* __restrict__ att_src,
    const float* __restrict__ att_dst, float* __restrict__ asrc,
    float* __restrict__ adst)
{
    int n = blockIdx.x * 8 + (threadIdx.x >> 5);
    int lane = threadIdx.x & 31;
    float s = 0.f, d = 0.f;
    #pragma unroll
    for (int q = 0; q < 4; q++) {
        int dd = lane + q * 32;
        float v = xl[n * HID + dd];
        s += v * att_src[dd];
        d += v * att_dst[dd];
    }
    #pragma unroll
    for (int o = 16; o > 0; o >>= 1) {
        s += __shfl_down_sync(0xffffffffu, s, o);
        d += __shfl_down_sync(0xffffffffu, d, o);
    }
    if (lane == 0) { asrc[n] = s; adst[n] = d; }
}

// ---------------- GAT with degenerate (NaN-topk) neighbor set ----------------
//   local n >= 16: neighbors {0..15}; + self loop
//   local n <  16: neighbors {0..16} each once
__global__ __launch_bounds__(256) void gat_k(
    const float* __restrict__ xl, const float* __restrict__ asrc,
    const float* __restrict__ adst, const float* __restrict__ gat_b,
    float* __restrict__ out)
{
    __shared__ float sx[KNN + 1][HID];
    __shared__ float ss[KNN + 1];

    const int nodebase = blockIdx.x * 8;
    const int g = nodebase / NP_G;
    const int base = g * NP_G;
    const int tid = threadIdx.x;

    for (int t = tid; t < (KNN + 1) * HID; t += 256)
        sx[t >> 7][t & 127] = xl[(base + (t >> 7)) * HID + (t & 127)];
    if (tid < KNN + 1) ss[tid] = asrc[base + tid];
    __syncthreads();

    const int warp = tid >> 5, lane = tid & 31;
    const int n = nodebase + warp;
    const int ln = n - base;
    const bool low = (ln < 16);
    const float adn = adst[n];

    float l = -1e30f;
    if (lane < 17) {
        float e = (low || lane < 16) ? ss[lane] : asrc[n];
        float z = e + adn;
        l = z >= 0.0f ? z : NEG_SLOPE * z;
    }
    float m = l;
    #pragma unroll
    for (int o = 16; o > 0; o >>= 1) m = fmaxf(m, __shfl_xor_sync(0xffffffffu, m, o));
    float w = (lane < 17) ? __expf(l - m) : 0.0f;
    float s = w;
    #pragma unroll
    for (int o = 16; o > 0; o >>= 1) s += __shfl_xor_sync(0xffffffffu, s, o);
    w /= s;

    float xn[4], acc[4] = {0.f, 0.f, 0.f, 0.f};
    #pragma unroll
    for (int q = 0; q < 4; q++) xn[q] = xl[n * HID + lane + q * 32];

    #pragma unroll
    for (int k = 0; k < 17; k++) {
        float wk = __shfl_sync(0xffffffffu, w, k);
        #pragma unroll
        for (int q = 0; q < 4; q++) {
            float v = (low || k < 16) ? sx[k][lane + q * 32] : xn[q];
            acc[q] += wk * v;
        }
    }
    #pragma unroll
    for (int q = 0; q < 4; q++) {
        int dd = lane + q * 32;
        out[n * HID + dd] = acc[q] + gat_b[dd];
    }
}

// ---------------- pair gather + labels, dtype-adaptive ----------------
__global__ __launch_bounds__(256) void pairs_k(
    const float* __restrict__ emb, const int* __restrict__ pidx,
    const float* __restrict__ labels, float* __restrict__ outp)
{
    int orv = 0;
    #pragma unroll
    for (int q = 0; q < 8; q++) orv |= pidx[2 * q + 1];
    const bool is64 = (orv == 0);

    long long rowid = (long long)blockIdx.x * 16 + (threadIdx.x >> 4);
    int lane = threadIdx.x & 15;
    const long long nrows = 2LL * NPAIRS;
    if (rowid < nrows) {
        int s = (int)(rowid / NPAIRS);
        int p = (int)(rowid - (long long)s * NPAIRS);
        int e = p * 2 + s;
        int node = is64 ? pidx[2 * e] : pidx[e];
        float4 v = *(const float4*)&emb[(long long)node * OUT_DIM + lane * 4];
        *(float4*)&outp[rowid * OUT_DIM + lane * 4] = v;
    } else {
        long long li = (rowid - nrows) * 16 + lane;
        if (li < NPAIRS)
            outp[2LL * NPAIRS * OUT_DIM + li] = labels[li];
    }
}

// ---------------- launch ----------------
extern "C" void kernel_launch(void* const* d_in, const int* in_sizes, int n_in,
                              void* d_out, int out_size)
{
    const float* x       = (const float*)d_in[0];
    const int*   pairs   = (const int*)d_in[2];
    const float* labels  = (const float*)d_in[3];
    const float* W0      = (const float*)d_in[4];
    const float* b0      = (const float*)d_in[5];
    const float* gatW    = (const float*)d_in[6];
    const float* att_src = (const float*)d_in[7];
    const float* att_dst = (const float*)d_in[8];
    const float* gatb    = (const float*)d_in[9];
    const float* W1      = (const float*)d_in[10];
    const float* b1      = (const float*)d_in[11];
    const float* W2      = (const float*)d_in[12];
    const float* b2      = (const float*)d_in[13];
    const float* W3      = (const float*)d_in[14];
    const float* b3      = (const float*)d_in[15];
    float* out = (float*)d_out;

    float *Wf, *bf, *xl, *asrc, *adst, *gat, *e1, *e2, *emb;
    cudaGetSymbolAddress((void**)&Wf,   g_Wf);
    cudaGetSymbolAddress((void**)&bf,   g_bf);
    cudaGetSymbolAddress((void**)&xl,   g_xl);
    cudaGetSymbolAddress((void**)&asrc, g_asrc);
    cudaGetSymbolAddress((void**)&adst, g_adst);
    cudaGetSymbolAddress((void**)&gat,  g_gat);
    cudaGetSymbolAddress((void**)&e1,   g_e1);
    cudaGetSymbolAddress((void**)&e2,   g_e2);
    cudaGetSymbolAddress((void**)&emb,  g_emb);

    const int M = N_NODES;

    // 0. fused weight: Wf = W0@gatW, bf = b0@gatW
    fuseW_k<<<IN_DIM + 1, HID>>>(W0, b0, gatW, Wf, bf);
    // 1. xl = x @ Wf + bf   (fp32; K=32, memory-bound)
    gemm_k<0><<<dim3(HID / 64, M / 128), 256>>>(x, Wf, bf, xl, M, IN_DIM, HID);
    // 2. a_src / a_dst
    attdot_k<<<M / 8, 256>>>(xl, att_src, att_dst, asrc, adst);
    // 3. attention aggregate
    gat_k<<<M / 8, 256>>>(xl, asrc, adst, gatb, gat);
    // 4. MLP on tensor cores (split-tf32, ~fp32 accuracy)
    gemm_tc_k<1><<<dim3(4 * HID / 64, M / 128), 256>>>(gat, W1, b1, e1, M, HID, 4 * HID);
    gemm_tc_k<1><<<dim3(2 * HID / 64, M / 128), 256>>>(e1, W2, b2, e2, M, 4 * HID, 2 * HID);
    gemm_tc_k<0><<<dim3(OUT_DIM / 64, M / 128), 256>>>(e2, W3, b3, emb, M, 2 * HID, OUT_DIM);
    // 5. gather pairs + labels
    long long nrows = 2LL * NPAIRS + (NPAIRS + 15) / 16;
    int nblk = (int)((nrows + 15) / 16);
    pairs_k<<<nblk, 256>>>(emb, pairs, labels, out);
}